// round 5
// baseline (speedup 1.0000x reference)
#include <cuda_runtime.h>
#include <cuda_fp16.h>
#include <cuda_fp8.h>

#define SEQ   1024
#define STEPS 1023
#define Hd    256
#define Bd    256
#define Cv    128
#define WSC   32768.0f
#define WINV  (1.0f/32768.0f)

// device scratch (no allocations allowed)
__device__ __align__(16) uint4 g_w8[12288];        // [3 gates][2 khalf][256 h][8 uint4], swizzled
__device__ float g_Tf[Cv*Hd], g_Ti[Cv*Hd], g_To[Cv*Hd], g_Gc[Cv*Hd];
__device__ float g_H[Hd*Bd];

__device__ __forceinline__ float sigm(float x){ return 1.0f/(1.0f+__expf(-x)); }

__device__ __forceinline__ void cvt16(uint4 v, __half2* o){
    __half2_raw r;
    r=__nv_cvt_fp8x2_to_halfraw2((__nv_fp8x2_storage_t)(v.x&0xFFFFu),__NV_E4M3); o[0]=*(__half2*)&r;
    r=__nv_cvt_fp8x2_to_halfraw2((__nv_fp8x2_storage_t)(v.x>>16),     __NV_E4M3); o[1]=*(__half2*)&r;
    r=__nv_cvt_fp8x2_to_halfraw2((__nv_fp8x2_storage_t)(v.y&0xFFFFu),__NV_E4M3); o[2]=*(__half2*)&r;
    r=__nv_cvt_fp8x2_to_halfraw2((__nv_fp8x2_storage_t)(v.y>>16),     __NV_E4M3); o[3]=*(__half2*)&r;
    r=__nv_cvt_fp8x2_to_halfraw2((__nv_fp8x2_storage_t)(v.z&0xFFFFu),__NV_E4M3); o[4]=*(__half2*)&r;
    r=__nv_cvt_fp8x2_to_halfraw2((__nv_fp8x2_storage_t)(v.z>>16),     __NV_E4M3); o[5]=*(__half2*)&r;
    r=__nv_cvt_fp8x2_to_halfraw2((__nv_fp8x2_storage_t)(v.w&0xFFFFu),__NV_E4M3); o[6]=*(__half2*)&r;
    r=__nv_cvt_fp8x2_to_halfraw2((__nv_fp8x2_storage_t)(v.w>>16),     __NV_E4M3); o[7]=*(__half2*)&r;
}

// dual-column dot: weight row chunk (K=128) vs c chunks of both columns
__device__ __forceinline__ void dot2(const uint4* wrow, int h, const __half* cb, int kh,
                                     float& s0, float& s1){
    const uint4* c0p=(const uint4*)(cb + kh*128);
    const uint4* c1p=(const uint4*)(cb + 256 + kh*128);
    __half2 z=__float2half2_rn(0.f), a0=z,b0=z,a1=z,b1=z;
#pragma unroll
    for(int j=0;j<8;j++){
        uint4 wv = wrow[(j+h)&7];
        __half2 wh[8]; cvt16(wv,wh);
        uint4 q0=c0p[2*j], q1=c0p[2*j+1], r0=c1p[2*j], r1=c1p[2*j+1];
        const __half2* cA=(const __half2*)&q0; const __half2* cB=(const __half2*)&q1;
        const __half2* dA=(const __half2*)&r0; const __half2* dB=(const __half2*)&r1;
#pragma unroll
        for(int t=0;t<4;t++){
            a0=__hfma2(wh[t],cA[t],a0);   b0=__hfma2(wh[4+t],cB[t],b0);
            a1=__hfma2(wh[t],dA[t],a1);   b1=__hfma2(wh[4+t],dB[t],b1);
        }
    }
    a0=__hadd2(a0,b0); a1=__hadd2(a1,b1);
    float2 f0=__half22float2(a0), f1=__half22float2(a1);
    s0=f0.x+f0.y; s1=f1.x+f1.y;
}

// token gate tables: Tf/Ti/To = {f,i,o}x @ emb[tok] + bias ; Gc = sigmoid(cx@emb + cb)
__global__ void tab_kernel(const float* __restrict__ emb,
                           const float* __restrict__ fx, const float* __restrict__ fb,
                           const float* __restrict__ ix, const float* __restrict__ ib,
                           const float* __restrict__ ox, const float* __restrict__ ob,
                           const float* __restrict__ cx, const float* __restrict__ cb){
    int tok=blockIdx.x, h=threadIdx.x;
    __shared__ float e[Cv];
    if(h<Cv) e[h]=emb[tok*Cv+h];
    __syncthreads();
    float af=0.f,ai=0.f,ao=0.f,ac=0.f;
#pragma unroll 4
    for(int c=0;c<Cv;c++){
        float ev=e[c];
        af=fmaf(fx[h*Cv+c],ev,af); ai=fmaf(ix[h*Cv+c],ev,ai);
        ao=fmaf(ox[h*Cv+c],ev,ao); ac=fmaf(cx[h*Cv+c],ev,ac);
    }
    g_Tf[tok*Hd+h]=af+fb[h]; g_Ti[tok*Hd+h]=ai+ib[h];
    g_To[tok*Hd+h]=ao+ob[h]; g_Gc[tok*Hd+h]=sigm(ac+cb[h]);
}

// pack fh/ih/oh into scaled e4m3, rotation-swizzled
__global__ void pack_kernel(const float* __restrict__ fh, const float* __restrict__ ih,
                            const float* __restrict__ oh){
    int id=blockIdx.x*256+threadIdx.x;            // 12288 total
    int g=id/4096, rem=id%4096, kh=rem/2048, r2=rem%2048, h=r2/8, j=r2%8;
    const float* src = (g==0)?fh:(g==1)?ih:oh;
    int kb = kh*128 + j*16;
    unsigned int u[4];
#pragma unroll
    for(int q=0;q<4;q++){
        unsigned int p=0;
#pragma unroll
        for(int t=0;t<4;t++){
            float v = src[h*Hd + kb + q*4 + t]*WSC;
            p |= ((unsigned int)__nv_cvt_float_to_fp8(v,__NV_SATFINITE,__NV_E4M3))<<(8*t);
        }
        u[q]=p;
    }
    g_w8[(g*2+kh)*2048 + h*8 + ((j+h)&7)] = make_uint4(u[0],u[1],u[2],u[3]);
}

__global__ __launch_bounds__(1024,1) void lstm_kernel(const int* __restrict__ x){
    extern __shared__ char smem[];
    uint4*   w8s=(uint4*)smem;                          // 196608 B
    __half*  cc =(__half*)(smem+196608);                // 2048 B: [2 buf][2 col][256]
    float2*  P  =(float2*)(smem+196608+2048);           // 8192 B: [4][256]
    int*     tk =(int*)(smem+196608+2048+8192);         // 8192 B: [2][1024]

    int tid=threadIdx.x;
    int b0=2*blockIdx.x, b1=b0+1;
    int g=tid>>9, kh=(tid>>8)&1, h=tid&255;
    const uint4* wrow = w8s + ((g*2+kh)*2048 + h*8);

    // load weights, tokens; zero c
#pragma unroll
    for(int q=0;q<12;q++) w8s[tid+q*1024]=g_w8[tid+q*1024];
    if(tid<STEPS){ tk[tid]=x[b0*SEQ+tid]; tk[1024+tid]=x[b1*SEQ+tid]; }
    if(tid<512) ((unsigned int*)cc)[tid]=0u;
    __syncthreads();

    float c0=0.f,c1=0.f, tf0=0,tf1=0,ti0=0,ti1=0,gc0=0,gc1=0;
    if(tid<256){
        int t0=tk[0], t1=tk[1024];
        tf0=__ldg(&g_Tf[t0*Hd+h]); tf1=__ldg(&g_Tf[t1*Hd+h]);
        ti0=__ldg(&g_Ti[t0*Hd+h]); ti1=__ldg(&g_Ti[t1*Hd+h]);
        gc0=__ldg(&g_Gc[t0*Hd+h]); gc1=__ldg(&g_Gc[t1*Hd+h]);
    }

    for(int s=0;s<STEPS;s++){
        const __half* ccur = cc + (s&1)*512;
        float s0,s1; dot2(wrow,h,ccur,kh,s0,s1);
        P[(g*2+kh)*256 + h] = make_float2(s0,s1);
        __syncthreads();
        if(tid<256){
            float2 pf0=P[h], pf1=P[256+h], pi0=P[512+h], pi1=P[768+h];
            float f0=sigm(tf0+(pf0.x+pf1.x)*WINV);
            float f1=sigm(tf1+(pf0.y+pf1.y)*WINV);
            float i0=sigm(ti0+(pi0.x+pi1.x)*WINV);
            float i1=sigm(ti1+(pi0.y+pi1.y)*WINV);
            c0=gc0*i0+c0*f0; c1=gc1*i1+c1*f1;
            __half* cn = cc + ((s+1)&1)*512;
            cn[h]=__float2half_rn(c0); cn[256+h]=__float2half_rn(c1);
            if(s+1<STEPS){  // prefetch next step's tables
                int t0=tk[s+1], t1=tk[1024+s+1];
                tf0=__ldg(&g_Tf[t0*Hd+h]); tf1=__ldg(&g_Tf[t1*Hd+h]);
                ti0=__ldg(&g_Ti[t0*Hd+h]); ti1=__ldg(&g_Ti[t1*Hd+h]);
                gc0=__ldg(&g_Gc[t0*Hd+h]); gc1=__ldg(&g_Gc[t1*Hd+h]);
            }
        }
        __syncthreads();
    }

    // output gate uses c_prev (= state before last step) in cc buf 0
    if(tid<512){
        int kh2=tid>>8, h2=tid&255;
        const uint4* orow = w8s + ((2*2+kh2)*2048 + h2*8);
        float s0,s1; dot2(orow,h2,cc,kh2,s0,s1);
        P[kh2*256+h2]=make_float2(s0,s1);
    }
    __syncthreads();
    if(tid<256){
        float2 p0=P[h], p1=P[256+h];
        int t0=tk[STEPS-1], t1=tk[1024+STEPS-1];
        float o0=sigm(__ldg(&g_To[t0*Hd+h]) + (p0.x+p1.x)*WINV);
        float o1=sigm(__ldg(&g_To[t1*Hd+h]) + (p0.y+p1.y)*WINV);
        g_H[h*Bd+b0]=tanhf(c0)*o0;
        g_H[h*Bd+b1]=tanhf(c1)*o1;
    }
}

// p = ph@H + pb ; softmax over batch ; out[b][c] = y[c][b]
__global__ void ep_kernel(const float* __restrict__ ph, const float* __restrict__ pb,
                          float* __restrict__ out){
    __shared__ float phr[Hd]; __shared__ float red[8];
    int c=blockIdx.x, b=threadIdx.x;
    phr[b]=ph[c*Hd+b];
    __syncthreads();
    float acc=pb[c];
#pragma unroll 8
    for(int k=0;k<Hd;k++) acc=fmaf(phr[k],__ldg(&g_H[k*Bd+b]),acc);
    float mx=acc;
    for(int o=16;o;o>>=1) mx=fmaxf(mx,__shfl_xor_sync(~0u,mx,o));
    if((b&31)==0) red[b>>5]=mx;
    __syncthreads();
    float m2=red[0];
#pragma unroll
    for(int w=1;w<8;w++) m2=fmaxf(m2,red[w]);
    float e=__expf(acc-m2), sm=e;
    for(int o=16;o;o>>=1) sm+=__shfl_xor_sync(~0u,sm,o);
    __syncthreads();
    if((b&31)==0) red[b>>5]=sm;
    __syncthreads();
    float tot=0.f;
#pragma unroll
    for(int w=0;w<8;w++) tot+=red[w];
    out[b*Cv+c]=e/tot;
}

extern "C" void kernel_launch(void* const* d_in, const int* in_sizes, int n_in,
                              void* d_out, int out_size){
    (void)in_sizes; (void)n_in; (void)out_size;
    const int*   x   =(const int*)  d_in[0];
    const float* emb =(const float*)d_in[1];
    const float* fx  =(const float*)d_in[2];
    const float* fh  =(const float*)d_in[3];
    const float* fb  =(const float*)d_in[4];
    const float* ix  =(const float*)d_in[5];
    const float* ih  =(const float*)d_in[6];
    const float* ib  =(const float*)d_in[7];
    const float* ox  =(const float*)d_in[8];
    const float* oh  =(const float*)d_in[9];
    const float* ob  =(const float*)d_in[10];
    const float* cx  =(const float*)d_in[11];
    const float* cb  =(const float*)d_in[12];
    const float* ph  =(const float*)d_in[13];
    const float* pb  =(const float*)d_in[14];
    float* out=(float*)d_out;

    static int inited=0;
    if(!inited){
        cudaFuncSetAttribute(lstm_kernel, cudaFuncAttributeMaxDynamicSharedMemorySize, 215040);
        inited=1;
    }
    tab_kernel<<<Cv,256>>>(emb,fx,fb,ix,ib,ox,ob,cx,cb);
    pack_kernel<<<48,256>>>(fh,ih,oh);
    lstm_kernel<<<128,1024,215040>>>(x);
    ep_kernel<<<Cv,Bd>>>(ph,pb,out);
}